// round 15
// baseline (speedup 1.0000x reference)
#include <cuda_runtime.h>
#include <cuda_bf16.h>
#include <cuda_fp16.h>
#include <math.h>
#include <stdint.h>

// ---------------------------------------------------------------------------
// SnakeScanBranch R14: R13 + fp16 dwconv intermediate (halves 201MB of
// front-end streaming traffic) + scanorm barrier batching (128 -> 32).
// ---------------------------------------------------------------------------

#define Bb 8
#define Cc 128
#define Hh 128
#define Ww 128
#define HW 16384
#define D_INNER 256
#define D_STATE 64
#define NHEADS 8
#define D_XBC 384
#define D_INPROJ 648
#define BS 1024
#define LL 128
#define MM 131072
#define OUT2D_ELEMS 16777216
#define OFF_ELEMS 131072
#define IPW_ELEMS (D_INPROJ * 128)
#define OW_ELEMS  (128 * D_INNER)

// ---- scratch ---------------------------------------------------------------
__device__ __half g_buf1[OUT2D_ELEMS];           // dwconv output (fp16)
__device__ __half g_z[(size_t)MM * 256];         // z (fp16)
__device__ __half g_xbcc[(size_t)MM * D_XBC];    // conv1d+silu output (fp16)
__device__ float g_dt[MM * NHEADS];
__device__ float g_off[OFF_ELEMS];
__device__ float g_part[64 * 8 * 2];
__device__ uint4 g_seq_h[(size_t)MM * 128 / 8];  // fp16 seq
__device__ uint4 g_y_h[(size_t)MM * 256 / 8];    // fp16 normalized y
__device__ uint4 g_ipw_hi[IPW_ELEMS / 8];
__device__ uint4 g_ipw_lo[IPW_ELEMS / 8];
__device__ uint4 g_ow_hi[OW_ELEMS / 8];
__device__ uint4 g_ow_lo[OW_ELEMS / 8];

// ---------------------------------------------------------------------------
__device__ __forceinline__ uint32_t smem_u32(const void* p) {
    uint32_t a;
    asm("{ .reg .u64 t; cvta.to.shared.u64 t, %1; cvt.u32.u64 %0, t; }"
        : "=r"(a) : "l"(p));
    return a;
}

#define LDSM4(r, addr)                                                        \
    asm volatile("ldmatrix.sync.aligned.m8n8.x4.shared.b16 {%0,%1,%2,%3}, [%4];" \
                 : "=r"((r)[0]), "=r"((r)[1]), "=r"((r)[2]), "=r"((r)[3])     \
                 : "r"(addr))

#define MMA_F16(d, a, b0, b1)                                                 \
    asm volatile(                                                             \
        "mma.sync.aligned.m16n8k16.row.col.f32.f16.f16.f32 "                  \
        "{%0,%1,%2,%3}, {%4,%5,%6,%7}, {%8,%9}, {%0,%1,%2,%3};"               \
        : "+f"((d)[0]), "+f"((d)[1]), "+f"((d)[2]), "+f"((d)[3])              \
        : "r"((a)[0]), "r"((a)[1]), "r"((a)[2]), "r"((a)[3]), "r"(b0), "r"(b1))

// packed f32x2 helpers
__device__ __forceinline__ unsigned long long pk2(float lo, float hi) {
    unsigned long long r;
    asm("mov.b64 %0, {%1, %2};" : "=l"(r) : "f"(lo), "f"(hi));
    return r;
}
__device__ __forceinline__ void upk2(unsigned long long v, float& lo, float& hi) {
    asm("mov.b64 {%0, %1}, %2;" : "=f"(lo), "=f"(hi) : "l"(v));
}
#define FMA2(d, a, b, c) \
    asm("fma.rn.f32x2 %0, %1, %2, %3;" : "=l"(d) : "l"(a), "l"(b), "l"(c))
#define MUL2(d, a, b) \
    asm("mul.rn.f32x2 %0, %1, %2;" : "=l"(d) : "l"(a), "l"(b))

// ---------------------------------------------------------------------------
// K1: depthwise 5x5 conv — 4 outputs/thread along y, fp16 output
// ---------------------------------------------------------------------------
__global__ __launch_bounds__(256) void k_dwconv(const float* __restrict__ x,
                                                const float* __restrict__ w) {
    int idx = blockIdx.x * 256 + threadIdx.x;
    int xx = idx & 127;
    int yg = (idx >> 7) & 31;
    int c  = (idx >> 12) & 127;
    int b  = idx >> 19;
    int y0 = yg * 4;
    float wr[25];
#pragma unroll
    for (int i = 0; i < 25; i++) wr[i] = __ldg(w + c * 25 + i);
    const float* plane = x + ((size_t)b * Cc + c) * HW;
    float o0 = 0.f, o1 = 0.f, o2 = 0.f, o3 = 0.f;
#pragma unroll
    for (int r = 0; r < 8; r++) {
        int sy = y0 + r - 2;
        if (sy < 0 || sy > 127) continue;
        const float* row = plane + sy * Ww;
        float v0 = (xx >= 2)   ? __ldg(row + xx - 2) : 0.f;
        float v1 = (xx >= 1)   ? __ldg(row + xx - 1) : 0.f;
        float v2 = __ldg(row + xx);
        float v3 = (xx <= 126) ? __ldg(row + xx + 1) : 0.f;
        float v4 = (xx <= 125) ? __ldg(row + xx + 2) : 0.f;
#define RS(ky) (v0 * wr[(ky) * 5 + 0] + v1 * wr[(ky) * 5 + 1] +               \
                v2 * wr[(ky) * 5 + 2] + v3 * wr[(ky) * 5 + 3] +               \
                v4 * wr[(ky) * 5 + 4])
        if (r <= 4)           o0 += RS(r);
        if (r >= 1 && r <= 5) o1 += RS(r - 1);
        if (r >= 2 && r <= 6) o2 += RS(r - 2);
        if (r >= 3)           o3 += RS(r - 3);
#undef RS
    }
    __half* dst = g_buf1 + ((size_t)b * Cc + c) * HW + y0 * Ww + xx;
    dst[0]      = __float2half(o0);
    dst[Ww]     = __float2half(o1);
    dst[2 * Ww] = __float2half(o2);
    dst[3 * Ww] = __float2half(o3);
}

// ---------------------------------------------------------------------------
// K2: groupnorm partial sums (uint4 = 8 halves per load)
// ---------------------------------------------------------------------------
__global__ __launch_bounds__(256) void k_gnstats1() {
    int bg = blockIdx.x;
    int part = blockIdx.y;
    const uint4* p = (const uint4*)(g_buf1 + (size_t)bg * 16 * HW + part * 32768);
    float s = 0.0f, ss = 0.0f;
    for (int i = threadIdx.x; i < 4096; i += 256) {
        uint4 v = p[i];
        const __half2* hp = (const __half2*)&v;
#pragma unroll
        for (int k = 0; k < 4; k++) {
            float2 f = __half22float2(hp[k]);
            s  += f.x + f.y;
            ss += f.x * f.x + f.y * f.y;
        }
    }
    __shared__ float rs[256], rss[256];
    rs[threadIdx.x] = s; rss[threadIdx.x] = ss;
    __syncthreads();
    for (int o = 128; o > 0; o >>= 1) {
        if (threadIdx.x < o) { rs[threadIdx.x] += rs[threadIdx.x + o]; rss[threadIdx.x] += rss[threadIdx.x + o]; }
        __syncthreads();
    }
    if (threadIdx.x == 0) {
        g_part[(bg * 8 + part) * 2]     = rs[0];
        g_part[(bg * 8 + part) * 2 + 1] = rss[0];
    }
}

// ---------------------------------------------------------------------------
// K3: finalize stats + gelu(gn) -> pointwise -> tanh*8  (2 px/thread, half2)
// ---------------------------------------------------------------------------
__global__ __launch_bounds__(256) void k_offset(const float* __restrict__ gn_g,
                                                const float* __restrict__ gn_b,
                                                const float* __restrict__ pw_w,
                                                const float* __restrict__ pw_b) {
    __shared__ float s_mean[8], s_rstd[8];
    int base = blockIdx.x * 512;
    int b = base >> 14;
    if (threadIdx.x < 8) {
        int gg = threadIdx.x;
        float s = 0.0f, ss = 0.0f;
        for (int p = 0; p < 8; p++) {
            s  += g_part[((b * 8 + gg) * 8 + p) * 2];
            ss += g_part[((b * 8 + gg) * 8 + p) * 2 + 1];
        }
        const float inv = 1.0f / (16.0f * HW);
        float mean = s * inv;
        float var  = ss * inv - mean * mean;
        s_mean[gg] = mean;
        s_rstd[gg] = rsqrtf(var + 1e-5f);
    }
    __syncthreads();
    int pixl = (base & 16383) + threadIdx.x * 2;
    const __half2* pb = (const __half2*)(g_buf1 + (size_t)b * Cc * HW);
    int p2 = pixl >> 1;
    float a0 = 0.0f, a1 = 0.0f;
    for (int c = 0; c < Cc; c++) {
        float2 v = __half22float2(pb[c * (HW / 2) + p2]);
        int grp = c >> 4;
        float mean = s_mean[grp], rstd = s_rstd[grp];
        float gw = __ldg(gn_g + c), gb = __ldg(gn_b + c);
        float pw = __ldg(pw_w + c);
        float u0 = (v.x - mean) * rstd * gw + gb;
        float u1 = (v.y - mean) * rstd * gw + gb;
        a0 += pw * (0.5f * u0 * (1.0f + erff(u0 * 0.70710678118654752440f)));
        a1 += pw * (0.5f * u1 * (1.0f + erff(u1 * 0.70710678118654752440f)));
    }
    float pb0 = __ldg(pw_b);
    int po = base + threadIdx.x * 2;
    g_off[po]     = tanhf(a0 + pb0) * 8.0f;
    g_off[po + 1] = tanhf(a1 + pb0) * 8.0f;
}

// ---------------------------------------------------------------------------
// K4: grid sample (bilinear, border) -> seq fp16 (half2 stores)
// ---------------------------------------------------------------------------
__global__ __launch_bounds__(256) void k_sample(const float* __restrict__ x) {
    int by = blockIdx.x;
    int b = by >> 7, y = by & 127;
    int x0g = blockIdx.y * 64;
    __shared__ float tile[64][129];
    __shared__ int s_y0[64], s_y1[64], s_x0[64], s_x1[64];
    __shared__ float s_wx[64], s_wy[64];
    int tid = threadIdx.x;
    if (tid < 64) {
        int xg = x0g + tid;
        float off_n = g_off[by * Ww + xg] * (2.0f / 127.0f);
        float byv = -1.0f + y  * (2.0f / 127.0f);
        float bxv = -1.0f + xg * (2.0f / 127.0f);
        float gyv = fminf(fmaxf(byv + off_n, -1.0f), 1.0f);
        float gx = fminf(fmaxf((bxv + 1.0f) * 0.5f * 127.0f, 0.0f), 127.0f);
        float gy = fminf(fmaxf((gyv + 1.0f) * 0.5f * 127.0f, 0.0f), 127.0f);
        float fx0 = floorf(gx), fy0 = floorf(gy);
        s_wx[tid] = gx - fx0;
        s_wy[tid] = gy - fy0;
        int x0i = (int)fx0, y0i = (int)fy0;
        s_x0[tid] = x0i; s_y0[tid] = y0i;
        s_x1[tid] = min(x0i + 1, 127);
        s_y1[tid] = min(y0i + 1, 127);
    }
    __syncthreads();
    for (int i = tid; i < 64 * Cc; i += 256) {
        int xl = i & 63;
        int c = i >> 6;
        const float* pl = x + ((size_t)b * Cc + c) * HW;
        float wx = s_wx[xl], wy = s_wy[xl];
        int r0 = s_y0[xl] * Ww, r1 = s_y1[xl] * Ww;
        float v00 = __ldg(pl + r0 + s_x0[xl]);
        float v01 = __ldg(pl + r0 + s_x1[xl]);
        float v10 = __ldg(pl + r1 + s_x0[xl]);
        float v11 = __ldg(pl + r1 + s_x1[xl]);
        float top = v00 * (1.0f - wx) + v01 * wx;
        float bot = v10 * (1.0f - wx) + v11 * wx;
        tile[xl][c] = top * (1.0f - wy) + bot * wy;
    }
    __syncthreads();
    __half2* sh2 = (__half2*)g_seq_h;
    for (int i = tid; i < 64 * 64; i += 256) {
        int xl = i >> 6;
        int c2 = i & 63;
        __half2 hv = __floats2half2_rn(tile[xl][c2 * 2], tile[xl][c2 * 2 + 1]);
        sh2[((size_t)by * Ww + x0g + xl) * 64 + c2] = hv;
    }
}

// ---------------------------------------------------------------------------
// Weight split fp32 -> fp16 hi + fp16 lo
// ---------------------------------------------------------------------------
__global__ __launch_bounds__(256) void k_wsplit(const float* __restrict__ w,
                                                uint4* __restrict__ hi4,
                                                uint4* __restrict__ lo4, int n) {
    int i = blockIdx.x * 256 + threadIdx.x;
    if (i >= n) return;
    float v = w[i];
    __half h = __float2half(v);
    __half l = __float2half(v - __half2float(h));
    ((__half*)hi4)[i] = h;
    ((__half*)lo4)[i] = l;
}

// ---------------------------------------------------------------------------
// fp16 GEMM (A single, B 2-product hi/lo): C = A * B^T
// ---------------------------------------------------------------------------
#define APAD 136
#define SM_A  0
#define SM_BH 34816
#define SM_BL 52224
#define SMEM_GEMM 69632

__global__ __launch_bounds__(256) void k_gemm(const uint4* __restrict__ A,
                                              const uint4* __restrict__ Bhi,
                                              const uint4* __restrict__ Blo,
                                              float* __restrict__ outp,
                                              const float* __restrict__ cw,
                                              const float* __restrict__ cb,
                                              const float* __restrict__ dtb,
                                              int N, int K, int mode) {
    extern __shared__ char sm[];
    uint32_t smb = smem_u32(sm);
    int tid = threadIdx.x;
    int lane = tid & 31;
    int wid = tid >> 5;
    int wm = (wid >> 1) * 32;
    int wn = (wid & 1) * 32;
    int m0 = blockIdx.y * 128;
    int n0 = blockIdx.x * 64;
    int K8 = K >> 3;

    float acc[2][4][4];
#pragma unroll
    for (int mi = 0; mi < 2; mi++)
#pragma unroll
        for (int ni = 0; ni < 4; ni++)
#pragma unroll
            for (int j = 0; j < 4; j++) acc[mi][ni][j] = 0.0f;

    int a_r  = lane & 15;
    int a_c8 = (lane >> 4) << 3;
    uint32_t a_base = ((uint32_t)(wm + a_r) * APAD + a_c8) * 2;
    int b_r  = (lane & 7) + ((lane >> 4) << 3);
    int b_c8 = ((lane >> 3) & 1) << 3;
    uint32_t b_base = ((uint32_t)(wn + b_r) * APAD + b_c8) * 2;

    int nchunks = K >> 7;
    for (int ch = 0; ch < nchunks; ch++) {
        if (ch) __syncthreads();
        int kc8 = ch << 4;
#pragma unroll
        for (int it = 0; it < 8; it++) {
            int g = it * 256 + tid;
            int row = g >> 4, kg = g & 15;
            size_t go = (size_t)(m0 + row) * K8 + kc8 + kg;
            uint32_t so = ((uint32_t)row * APAD + kg * 8) * 2;
            *(uint4*)(sm + SM_A + so) = A[go];
        }
#pragma unroll
        for (int it = 0; it < 4; it++) {
            int g = it * 256 + tid;
            int row = g >> 4, kg = g & 15;
            uint4 h = make_uint4(0, 0, 0, 0), l = make_uint4(0, 0, 0, 0);
            if (n0 + row < N) {
                size_t go = (size_t)(n0 + row) * K8 + kc8 + kg;
                h = Bhi[go]; l = Blo[go];
            }
            uint32_t so = ((uint32_t)row * APAD + kg * 8) * 2;
            *(uint4*)(sm + SM_BH + so) = h;
            *(uint4*)(sm + SM_BL + so) = l;
        }
        __syncthreads();
#pragma unroll
        for (int k16 = 0; k16 < 8; k16++) {
            uint32_t kb2 = (uint32_t)(k16 * 16) * 2;
            uint32_t Ah[2][4], Bh[2][4], Bl[2][4];
#pragma unroll
            for (int mi = 0; mi < 2; mi++) {
                uint32_t ad = smb + a_base + (uint32_t)mi * (16 * APAD * 2) + kb2;
                LDSM4(Ah[mi], ad + SM_A);
            }
#pragma unroll
            for (int nj = 0; nj < 2; nj++) {
                uint32_t bd = smb + b_base + (uint32_t)nj * (16 * APAD * 2) + kb2;
                LDSM4(Bh[nj], bd + SM_BH);
                LDSM4(Bl[nj], bd + SM_BL);
            }
#pragma unroll
            for (int mi = 0; mi < 2; mi++)
#pragma unroll
                for (int nj = 0; nj < 2; nj++) {
                    MMA_F16(acc[mi][2 * nj + 0], Ah[mi], Bh[nj][0], Bh[nj][1]);
                    MMA_F16(acc[mi][2 * nj + 0], Ah[mi], Bl[nj][0], Bl[nj][1]);
                    MMA_F16(acc[mi][2 * nj + 1], Ah[mi], Bh[nj][2], Bh[nj][3]);
                    MMA_F16(acc[mi][2 * nj + 1], Ah[mi], Bl[nj][2], Bl[nj][3]);
                }
        }
    }

    // ---- fused epilogues ----
    __syncthreads();
    float* st = (float*)sm;
    int g = lane >> 2, t = lane & 3;

    if (mode == 2) {
#pragma unroll
        for (int mi = 0; mi < 2; mi++)
#pragma unroll
            for (int ni = 0; ni < 4; ni++) {
                int r = wm + mi * 16 + g;
                int c = wn + ni * 8 + t * 2;
                st[c * 132 + r]           = acc[mi][ni][0];
                st[(c + 1) * 132 + r]     = acc[mi][ni][1];
                st[c * 132 + r + 8]       = acc[mi][ni][2];
                st[(c + 1) * 132 + r + 8] = acc[mi][ni][3];
            }
        __syncthreads();
        int seq = m0 >> 7;
        int b = seq >> 7, y = seq & 127;
#pragma unroll
        for (int j = 0; j < 32; j++) {
            int idx = j * 256 + tid;
            int c = idx >> 7, xx = idx & 127;
            outp[(((size_t)b * 128 + n0 + c) * 128 + y) * 128 + xx] = st[c * 132 + xx];
        }
        return;
    }

    // mode 1: stage [l][e] (pad 72)
#pragma unroll
    for (int mi = 0; mi < 2; mi++)
#pragma unroll
        for (int ni = 0; ni < 4; ni++) {
            int r = wm + mi * 16 + g;
            int c = wn + ni * 8 + t * 2;
            *(float2*)&st[r * 72 + c] = make_float2(acc[mi][ni][0], acc[mi][ni][1]);
            *(float2*)&st[(r + 8) * 72 + c] = make_float2(acc[mi][ni][2], acc[mi][ni][3]);
        }
    __syncthreads();

    if (n0 < 256) {
        __half2* dst = (__half2*)g_z;
#pragma unroll
        for (int j = 0; j < 16; j++) {
            int idx = j * 256 + tid;
            int r = idx >> 5, cp = idx & 31;
            float2 v = *(float2*)&st[r * 72 + cp * 2];
            dst[(size_t)(m0 + r) * 128 + (n0 >> 1) + cp] = __floats2half2_rn(v.x, v.y);
        }
    } else if (n0 < 640) {
        int e2 = tid & 31;
        int ea = e2 * 2, eb = ea + 1;
        int eg = n0 - 256 + ea;
        float4 wA = *(const float4*)(cw + eg * 4);
        float4 wB = *(const float4*)(cw + eg * 4 + 4);
        float biaA = __ldg(cb + eg);
        float biaB = __ldg(cb + eg + 1);
        int lb = (tid >> 5) * 16;
        float a0 = (lb >= 3) ? st[(lb - 3) * 72 + ea] : 0.0f;
        float a1 = (lb >= 2) ? st[(lb - 2) * 72 + ea] : 0.0f;
        float a2 = (lb >= 1) ? st[(lb - 1) * 72 + ea] : 0.0f;
        float b0 = (lb >= 3) ? st[(lb - 3) * 72 + eb] : 0.0f;
        float b1 = (lb >= 2) ? st[(lb - 2) * 72 + eb] : 0.0f;
        float b2 = (lb >= 1) ? st[(lb - 1) * 72 + eb] : 0.0f;
        __half2* dst = (__half2*)g_xbcc;
        int colbase = ((n0 - 256) >> 1) + e2;
#pragma unroll 4
        for (int l = lb; l < lb + 16; l++) {
            float a3 = st[l * 72 + ea];
            float b3 = st[l * 72 + eb];
            float va = biaA + wA.x * a0 + wA.y * a1 + wA.z * a2 + wA.w * a3;
            float vb = biaB + wB.x * b0 + wB.y * b1 + wB.z * b2 + wB.w * b3;
            a0 = a1; a1 = a2; a2 = a3;
            b0 = b1; b1 = b2; b2 = b3;
            va = va / (1.0f + expf(-va));
            vb = vb / (1.0f + expf(-vb));
            dst[(size_t)(m0 + l) * 192 + colbase] = __floats2half2_rn(va, vb);
        }
    } else {
#pragma unroll
        for (int j = 0; j < 4; j++) {
            int idx = j * 256 + tid;
            int r = idx >> 3, hc = idx & 7;
            float v = st[r * 72 + hc] + __ldg(dtb + hc);
            g_dt[(size_t)(m0 + r) * 8 + hc] =
                fmaxf(v, 0.0f) + log1pf(expf(-fabsf(v)));
        }
    }
}

// ---------------------------------------------------------------------------
// K7: fused selective scan + gated RMSNorm, f32x2 inner loop, 4-step batched
// normalization reductions (1 barrier per 4 timesteps, double-buffered).
// ---------------------------------------------------------------------------
#define SCANORM_SMEM ((8192 + 8192 + 1024 + 1024 + 64) * 4)
__global__ __launch_bounds__(256) void k_scanorm(const float* __restrict__ A_log,
                                                 const float* __restrict__ Dskip,
                                                 const float* __restrict__ ng) {
    extern __shared__ float smf[];
    float* sB  = smf;
    float* sC  = sB + 8192;
    float* sdt = sC + 8192;
    float* sdA = sdt + 1024;
    float* pp  = sdA + 1024;          // [2][4][8]
    int bs = blockIdx.x;
    int t = threadIdx.x;
    int hh = t >> 5;
    int lane = t & 31, wid = t >> 5;

    const __half* xb = g_xbcc + (size_t)bs * 128 * 384;
    const __half2* xb2 = (const __half2*)xb;
    for (int i = t; i < 4096; i += 256) {
        int l = i >> 5, s2 = i & 31;
        float2 fb = __half22float2(xb2[l * 192 + 128 + s2]);
        float2 fc = __half22float2(xb2[l * 192 + 160 + s2]);
        sB[l * 64 + 2 * s2]     = fb.x;
        sB[l * 64 + 2 * s2 + 1] = fb.y;
        sC[l * 64 + 2 * s2]     = fc.x;
        sC[l * 64 + 2 * s2 + 1] = fc.y;
    }
    for (int i = t; i < 1024; i += 256) {
        int l = i >> 3, h = i & 7;
        float v = g_dt[((size_t)bs * 128 + l) * 8 + h];
        sdt[i] = v;
        sdA[i] = expf(v * (-expf(__ldg(A_log + h))));
    }
    __syncthreads();

    float Dh = __ldg(Dskip + hh);
    float gn = __ldg(ng + t);
    unsigned long long h2[32];
#pragma unroll
    for (int s = 0; s < 32; s++) h2[s] = 0ULL;
    __half* yh = (__half*)g_y_h;

    for (int lb = 0; lb < 128; lb += 4) {
        float gvv[4];
        float* ppb = pp + ((lb >> 2) & 1) * 32;
#pragma unroll
        for (int j = 0; j < 4; j++) {
            int l = lb + j;
            float xv  = __half2float(xb[l * 384 + t]);
            float z   = __half2float(g_z[((size_t)bs * 128 + l) * 256 + t]);
            float dtv = sdt[l * 8 + hh];
            float dA  = sdA[l * 8 + hh];
            float cf  = dtv * xv;
            unsigned long long dA2 = pk2(dA, dA);
            unsigned long long cf2 = pk2(cf, cf);
            const unsigned long long* B2 = (const unsigned long long*)(sB + l * 64);
            const unsigned long long* C2 = (const unsigned long long*)(sC + l * 64);
            unsigned long long y2 = 0ULL;
#pragma unroll
            for (int s = 0; s < 32; s++) {
                unsigned long long bb = B2[s], cc = C2[s], u;
                MUL2(u, cf2, bb);
                FMA2(h2[s], h2[s], dA2, u);
                FMA2(y2, h2[s], cc, y2);
            }
            float y0, y1;
            upk2(y2, y0, y1);
            float y = (y0 + y1) + Dh * xv;
            float gv = y * (z / (1.0f + expf(-z)));
            gvv[j] = gv;
            float g2 = gv * gv;
#pragma unroll
            for (int o = 16; o > 0; o >>= 1) g2 += __shfl_xor_sync(0xffffffffu, g2, o);
            if (lane == 0) ppb[j * 8 + wid] = g2;
        }
        __syncthreads();
#pragma unroll
        for (int j = 0; j < 4; j++) {
            const float* q = ppb + j * 8;
            float sum = q[0] + q[1] + q[2] + q[3] + q[4] + q[5] + q[6] + q[7];
            float sc = rsqrtf(sum * (1.0f / 256.0f) + 1e-5f);
            yh[((size_t)bs * 128 + lb + j) * 256 + t] = __float2half(gvv[j] * sc * gn);
        }
        // next batch writes the other pp buffer; its sync orders reads/writes
    }
}

// ---------------------------------------------------------------------------
extern "C" void kernel_launch(void* const* d_in, const int* in_sizes, int n_in,
                              void* d_out, int out_size) {
    const float* x        = (const float*)d_in[0];
    const float* dw_w     = (const float*)d_in[1];
    const float* gn_g     = (const float*)d_in[2];
    const float* gn_b     = (const float*)d_in[3];
    const float* pw_w     = (const float*)d_in[4];
    const float* pw_b     = (const float*)d_in[5];
    const float* in_projw = (const float*)d_in[6];
    const float* conv_w   = (const float*)d_in[7];
    const float* conv_b   = (const float*)d_in[8];
    const float* dt_bias  = (const float*)d_in[9];
    const float* A_log    = (const float*)d_in[10];
    const float* D_skip   = (const float*)d_in[11];
    const float* norm_g   = (const float*)d_in[12];
    const float* out_w    = (const float*)d_in[13];
    float* out = (float*)d_out;

    float* p_off;
    uint4 *p_sh, *p_yh, *p_iph, *p_ipl, *p_owh, *p_owl;
    cudaGetSymbolAddress((void**)&p_off, g_off);
    cudaGetSymbolAddress((void**)&p_sh, g_seq_h);
    cudaGetSymbolAddress((void**)&p_yh, g_y_h);
    cudaGetSymbolAddress((void**)&p_iph, g_ipw_hi);
    cudaGetSymbolAddress((void**)&p_ipl, g_ipw_lo);
    cudaGetSymbolAddress((void**)&p_owh, g_ow_hi);
    cudaGetSymbolAddress((void**)&p_owl, g_ow_lo);

    cudaFuncSetAttribute(k_gemm, cudaFuncAttributeMaxDynamicSharedMemorySize, SMEM_GEMM);
    cudaFuncSetAttribute(k_scanorm, cudaFuncAttributeMaxDynamicSharedMemorySize, SCANORM_SMEM);

    k_dwconv<<<OUT2D_ELEMS / 4 / 256, 256>>>(x, dw_w);
    k_gnstats1<<<dim3(64, 8), 256>>>();
    k_offset<<<OFF_ELEMS / 512, 256>>>(gn_g, gn_b, pw_w, pw_b);
    k_sample<<<dim3(BS, 2), 256>>>(x);
    k_wsplit<<<(IPW_ELEMS + 255) / 256, 256>>>(in_projw, p_iph, p_ipl, IPW_ELEMS);

    // in_proj: (M=131072, N=648, K=128) + fused conv1d/silu/dt epilogue
    k_gemm<<<dim3((D_INPROJ + 63) / 64, MM / 128), 256, SMEM_GEMM>>>(
        p_sh, p_iph, p_ipl, nullptr, conv_w, conv_b, dt_bias,
        D_INPROJ, 128, 1);

    k_wsplit<<<(OW_ELEMS + 255) / 256, 256>>>(out_w, p_owh, p_owl, OW_ELEMS);

    // fused scan + gated RMSNorm
    k_scanorm<<<BS, 256, SCANORM_SMEM>>>(A_log, D_skip, norm_g);

    // out proj: (M=131072, N=128, K=256) + fused NCHW epilogue
    k_gemm<<<dim3(2, MM / 128), 256, SMEM_GEMM>>>(
        p_yh, p_owh, p_owl, out, nullptr, nullptr, nullptr,
        128, 256, 2);

    if (out_size >= OUT2D_ELEMS + OFF_ELEMS)
        cudaMemcpyAsync(out + OUT2D_ELEMS, p_off, OFF_ELEMS * sizeof(float),
                        cudaMemcpyDeviceToDevice);
}

// round 16
// speedup vs baseline: 1.3629x; 1.3629x over previous
#include <cuda_runtime.h>
#include <cuda_bf16.h>
#include <cuda_fp16.h>
#include <math.h>
#include <stdint.h>

// ---------------------------------------------------------------------------
// SnakeScanBranch R15: exact R13 pipeline (known-good 1137us / 4.64e-4)
// + k_offset 4px/thread float4 loads. R14's fp16 buf1 and scan batching
// reverted (spill + accuracy regressions).
// ---------------------------------------------------------------------------

#define Bb 8
#define Cc 128
#define Hh 128
#define Ww 128
#define HW 16384
#define D_INNER 256
#define D_STATE 64
#define NHEADS 8
#define D_XBC 384
#define D_INPROJ 648
#define BS 1024
#define LL 128
#define MM 131072
#define OUT2D_ELEMS 16777216
#define OFF_ELEMS 131072
#define IPW_ELEMS (D_INPROJ * 128)
#define OW_ELEMS  (128 * D_INNER)

// ---- scratch ---------------------------------------------------------------
__device__ float g_buf1[OUT2D_ELEMS];            // dwconv output (fp32)
__device__ __half g_z[(size_t)MM * 256];         // z (fp16)
__device__ __half g_xbcc[(size_t)MM * D_XBC];    // conv1d+silu output (fp16)
__device__ float g_dt[MM * NHEADS];
__device__ float g_off[OFF_ELEMS];
__device__ float g_part[64 * 8 * 2];
__device__ uint4 g_seq_h[(size_t)MM * 128 / 8];  // fp16 seq
__device__ uint4 g_y_h[(size_t)MM * 256 / 8];    // fp16 normalized y
__device__ uint4 g_ipw_hi[IPW_ELEMS / 8];
__device__ uint4 g_ipw_lo[IPW_ELEMS / 8];
__device__ uint4 g_ow_hi[OW_ELEMS / 8];
__device__ uint4 g_ow_lo[OW_ELEMS / 8];

// ---------------------------------------------------------------------------
__device__ __forceinline__ uint32_t smem_u32(const void* p) {
    uint32_t a;
    asm("{ .reg .u64 t; cvta.to.shared.u64 t, %1; cvt.u32.u64 %0, t; }"
        : "=r"(a) : "l"(p));
    return a;
}

#define LDSM4(r, addr)                                                        \
    asm volatile("ldmatrix.sync.aligned.m8n8.x4.shared.b16 {%0,%1,%2,%3}, [%4];" \
                 : "=r"((r)[0]), "=r"((r)[1]), "=r"((r)[2]), "=r"((r)[3])     \
                 : "r"(addr))

#define MMA_F16(d, a, b0, b1)                                                 \
    asm volatile(                                                             \
        "mma.sync.aligned.m16n8k16.row.col.f32.f16.f16.f32 "                  \
        "{%0,%1,%2,%3}, {%4,%5,%6,%7}, {%8,%9}, {%0,%1,%2,%3};"               \
        : "+f"((d)[0]), "+f"((d)[1]), "+f"((d)[2]), "+f"((d)[3])              \
        : "r"((a)[0]), "r"((a)[1]), "r"((a)[2]), "r"((a)[3]), "r"(b0), "r"(b1))

// packed f32x2 helpers
__device__ __forceinline__ unsigned long long pk2(float lo, float hi) {
    unsigned long long r;
    asm("mov.b64 %0, {%1, %2};" : "=l"(r) : "f"(lo), "f"(hi));
    return r;
}
__device__ __forceinline__ void upk2(unsigned long long v, float& lo, float& hi) {
    asm("mov.b64 {%0, %1}, %2;" : "=f"(lo), "=f"(hi) : "l"(v));
}
#define FMA2(d, a, b, c) \
    asm("fma.rn.f32x2 %0, %1, %2, %3;" : "=l"(d) : "l"(a), "l"(b), "l"(c))
#define MUL2(d, a, b) \
    asm("mul.rn.f32x2 %0, %1, %2;" : "=l"(d) : "l"(a), "l"(b))

// ---------------------------------------------------------------------------
// K1: depthwise 5x5 conv — 4 outputs/thread along y (row-tap reuse)
// ---------------------------------------------------------------------------
__global__ __launch_bounds__(256) void k_dwconv(const float* __restrict__ x,
                                                const float* __restrict__ w) {
    int idx = blockIdx.x * 256 + threadIdx.x;
    int xx = idx & 127;
    int yg = (idx >> 7) & 31;
    int c  = (idx >> 12) & 127;
    int b  = idx >> 19;
    int y0 = yg * 4;
    float wr[25];
#pragma unroll
    for (int i = 0; i < 25; i++) wr[i] = __ldg(w + c * 25 + i);
    const float* plane = x + ((size_t)b * Cc + c) * HW;
    float o0 = 0.f, o1 = 0.f, o2 = 0.f, o3 = 0.f;
#pragma unroll
    for (int r = 0; r < 8; r++) {
        int sy = y0 + r - 2;
        if (sy < 0 || sy > 127) continue;
        const float* row = plane + sy * Ww;
        float v0 = (xx >= 2)   ? __ldg(row + xx - 2) : 0.f;
        float v1 = (xx >= 1)   ? __ldg(row + xx - 1) : 0.f;
        float v2 = __ldg(row + xx);
        float v3 = (xx <= 126) ? __ldg(row + xx + 1) : 0.f;
        float v4 = (xx <= 125) ? __ldg(row + xx + 2) : 0.f;
#define RS(ky) (v0 * wr[(ky) * 5 + 0] + v1 * wr[(ky) * 5 + 1] +               \
                v2 * wr[(ky) * 5 + 2] + v3 * wr[(ky) * 5 + 3] +               \
                v4 * wr[(ky) * 5 + 4])
        if (r <= 4)           o0 += RS(r);
        if (r >= 1 && r <= 5) o1 += RS(r - 1);
        if (r >= 2 && r <= 6) o2 += RS(r - 2);
        if (r >= 3)           o3 += RS(r - 3);
#undef RS
    }
    float* dst = g_buf1 + ((size_t)b * Cc + c) * HW + y0 * Ww + xx;
    dst[0]       = o0;
    dst[Ww]      = o1;
    dst[2 * Ww]  = o2;
    dst[3 * Ww]  = o3;
}

// ---------------------------------------------------------------------------
// K2: groupnorm partial sums (float4 streaming)
// ---------------------------------------------------------------------------
__global__ __launch_bounds__(256) void k_gnstats1() {
    int bg = blockIdx.x;
    int part = blockIdx.y;
    const float4* p = (const float4*)(g_buf1 + (size_t)bg * 16 * HW + part * 32768);
    float s = 0.0f, ss = 0.0f;
    for (int i = threadIdx.x; i < 8192; i += 256) {
        float4 v = p[i];
        s  += (v.x + v.y) + (v.z + v.w);
        ss += (v.x * v.x + v.y * v.y) + (v.z * v.z + v.w * v.w);
    }
    __shared__ float rs[256], rss[256];
    rs[threadIdx.x] = s; rss[threadIdx.x] = ss;
    __syncthreads();
    for (int o = 128; o > 0; o >>= 1) {
        if (threadIdx.x < o) { rs[threadIdx.x] += rs[threadIdx.x + o]; rss[threadIdx.x] += rss[threadIdx.x + o]; }
        __syncthreads();
    }
    if (threadIdx.x == 0) {
        g_part[(bg * 8 + part) * 2]     = rs[0];
        g_part[(bg * 8 + part) * 2 + 1] = rss[0];
    }
}

// ---------------------------------------------------------------------------
// K3: finalize stats + gelu(gn) -> pointwise -> tanh*8  (4 px/thread, float4)
// ---------------------------------------------------------------------------
__global__ __launch_bounds__(256) void k_offset(const float* __restrict__ gn_g,
                                                const float* __restrict__ gn_b,
                                                const float* __restrict__ pw_w,
                                                const float* __restrict__ pw_b) {
    __shared__ float s_mean[8], s_rstd[8];
    int base = blockIdx.x * 1024;                // 128 blocks x 1024 px
    int b = base >> 14;
    if (threadIdx.x < 8) {
        int gg = threadIdx.x;
        float s = 0.0f, ss = 0.0f;
        for (int p = 0; p < 8; p++) {
            s  += g_part[((b * 8 + gg) * 8 + p) * 2];
            ss += g_part[((b * 8 + gg) * 8 + p) * 2 + 1];
        }
        const float inv = 1.0f / (16.0f * HW);
        float mean = s * inv;
        float var  = ss * inv - mean * mean;
        s_mean[gg] = mean;
        s_rstd[gg] = rsqrtf(var + 1e-5f);
    }
    __syncthreads();
    int pixl = (base & 16383) + threadIdx.x * 4;
    const float* pb = g_buf1 + (size_t)b * Cc * HW + pixl;
    float a0 = 0.0f, a1 = 0.0f, a2 = 0.0f, a3 = 0.0f;
    for (int c = 0; c < Cc; c++) {
        float4 v = *(const float4*)(pb + (size_t)c * HW);
        int grp = c >> 4;
        float mean = s_mean[grp], rstd = s_rstd[grp];
        float gw = __ldg(gn_g + c), gb = __ldg(gn_b + c);
        float pw = __ldg(pw_w + c);
        float u0 = (v.x - mean) * rstd * gw + gb;
        float u1 = (v.y - mean) * rstd * gw + gb;
        float u2 = (v.z - mean) * rstd * gw + gb;
        float u3 = (v.w - mean) * rstd * gw + gb;
        a0 += pw * (0.5f * u0 * (1.0f + erff(u0 * 0.70710678118654752440f)));
        a1 += pw * (0.5f * u1 * (1.0f + erff(u1 * 0.70710678118654752440f)));
        a2 += pw * (0.5f * u2 * (1.0f + erff(u2 * 0.70710678118654752440f)));
        a3 += pw * (0.5f * u3 * (1.0f + erff(u3 * 0.70710678118654752440f)));
    }
    float pb0 = __ldg(pw_b);
    int po = base + threadIdx.x * 4;
    g_off[po]     = tanhf(a0 + pb0) * 8.0f;
    g_off[po + 1] = tanhf(a1 + pb0) * 8.0f;
    g_off[po + 2] = tanhf(a2 + pb0) * 8.0f;
    g_off[po + 3] = tanhf(a3 + pb0) * 8.0f;
}

// ---------------------------------------------------------------------------
// K4: grid sample (bilinear, border) -> seq fp16 (half2 stores)
// ---------------------------------------------------------------------------
__global__ __launch_bounds__(256) void k_sample(const float* __restrict__ x) {
    int by = blockIdx.x;
    int b = by >> 7, y = by & 127;
    int x0g = blockIdx.y * 64;
    __shared__ float tile[64][129];
    __shared__ int s_y0[64], s_y1[64], s_x0[64], s_x1[64];
    __shared__ float s_wx[64], s_wy[64];
    int tid = threadIdx.x;
    if (tid < 64) {
        int xg = x0g + tid;
        float off_n = g_off[by * Ww + xg] * (2.0f / 127.0f);
        float byv = -1.0f + y  * (2.0f / 127.0f);
        float bxv = -1.0f + xg * (2.0f / 127.0f);
        float gyv = fminf(fmaxf(byv + off_n, -1.0f), 1.0f);
        float gx = fminf(fmaxf((bxv + 1.0f) * 0.5f * 127.0f, 0.0f), 127.0f);
        float gy = fminf(fmaxf((gyv + 1.0f) * 0.5f * 127.0f, 0.0f), 127.0f);
        float fx0 = floorf(gx), fy0 = floorf(gy);
        s_wx[tid] = gx - fx0;
        s_wy[tid] = gy - fy0;
        int x0i = (int)fx0, y0i = (int)fy0;
        s_x0[tid] = x0i; s_y0[tid] = y0i;
        s_x1[tid] = min(x0i + 1, 127);
        s_y1[tid] = min(y0i + 1, 127);
    }
    __syncthreads();
    for (int i = tid; i < 64 * Cc; i += 256) {
        int xl = i & 63;
        int c = i >> 6;
        const float* pl = x + ((size_t)b * Cc + c) * HW;
        float wx = s_wx[xl], wy = s_wy[xl];
        int r0 = s_y0[xl] * Ww, r1 = s_y1[xl] * Ww;
        float v00 = __ldg(pl + r0 + s_x0[xl]);
        float v01 = __ldg(pl + r0 + s_x1[xl]);
        float v10 = __ldg(pl + r1 + s_x0[xl]);
        float v11 = __ldg(pl + r1 + s_x1[xl]);
        float top = v00 * (1.0f - wx) + v01 * wx;
        float bot = v10 * (1.0f - wx) + v11 * wx;
        tile[xl][c] = top * (1.0f - wy) + bot * wy;
    }
    __syncthreads();
    __half2* sh2 = (__half2*)g_seq_h;
    for (int i = tid; i < 64 * 64; i += 256) {
        int xl = i >> 6;
        int c2 = i & 63;
        __half2 hv = __floats2half2_rn(tile[xl][c2 * 2], tile[xl][c2 * 2 + 1]);
        sh2[((size_t)by * Ww + x0g + xl) * 64 + c2] = hv;
    }
}

// ---------------------------------------------------------------------------
// Weight split fp32 -> fp16 hi + fp16 lo
// ---------------------------------------------------------------------------
__global__ __launch_bounds__(256) void k_wsplit(const float* __restrict__ w,
                                                uint4* __restrict__ hi4,
                                                uint4* __restrict__ lo4, int n) {
    int i = blockIdx.x * 256 + threadIdx.x;
    if (i >= n) return;
    float v = w[i];
    __half h = __float2half(v);
    __half l = __float2half(v - __half2float(h));
    ((__half*)hi4)[i] = h;
    ((__half*)lo4)[i] = l;
}

// ---------------------------------------------------------------------------
// fp16 GEMM (A single, B 2-product hi/lo): C = A * B^T
// mode 1: in_proj fused epilogue (z half2 / conv1d+silu half2 / dt fp32).
// mode 2: out proj, direct NCHW epilogue.
// ---------------------------------------------------------------------------
#define APAD 136
#define SM_A  0
#define SM_BH 34816
#define SM_BL 52224
#define SMEM_GEMM 69632

__global__ __launch_bounds__(256) void k_gemm(const uint4* __restrict__ A,
                                              const uint4* __restrict__ Bhi,
                                              const uint4* __restrict__ Blo,
                                              float* __restrict__ outp,
                                              const float* __restrict__ cw,
                                              const float* __restrict__ cb,
                                              const float* __restrict__ dtb,
                                              int N, int K, int mode) {
    extern __shared__ char sm[];
    uint32_t smb = smem_u32(sm);
    int tid = threadIdx.x;
    int lane = tid & 31;
    int wid = tid >> 5;
    int wm = (wid >> 1) * 32;
    int wn = (wid & 1) * 32;
    int m0 = blockIdx.y * 128;
    int n0 = blockIdx.x * 64;
    int K8 = K >> 3;

    float acc[2][4][4];
#pragma unroll
    for (int mi = 0; mi < 2; mi++)
#pragma unroll
        for (int ni = 0; ni < 4; ni++)
#pragma unroll
            for (int j = 0; j < 4; j++) acc[mi][ni][j] = 0.0f;

    int a_r  = lane & 15;
    int a_c8 = (lane >> 4) << 3;
    uint32_t a_base = ((uint32_t)(wm + a_r) * APAD + a_c8) * 2;
    int b_r  = (lane & 7) + ((lane >> 4) << 3);
    int b_c8 = ((lane >> 3) & 1) << 3;
    uint32_t b_base = ((uint32_t)(wn + b_r) * APAD + b_c8) * 2;

    int nchunks = K >> 7;
    for (int ch = 0; ch < nchunks; ch++) {
        if (ch) __syncthreads();
        int kc8 = ch << 4;
#pragma unroll
        for (int it = 0; it < 8; it++) {
            int g = it * 256 + tid;
            int row = g >> 4, kg = g & 15;
            size_t go = (size_t)(m0 + row) * K8 + kc8 + kg;
            uint32_t so = ((uint32_t)row * APAD + kg * 8) * 2;
            *(uint4*)(sm + SM_A + so) = A[go];
        }
#pragma unroll
        for (int it = 0; it < 4; it++) {
            int g = it * 256 + tid;
            int row = g >> 4, kg = g & 15;
            uint4 h = make_uint4(0, 0, 0, 0), l = make_uint4(0, 0, 0, 0);
            if (n0 + row < N) {
                size_t go = (size_t)(n0 + row) * K8 + kc8 + kg;
                h = Bhi[go]; l = Blo[go];
            }
            uint32_t so = ((uint32_t)row * APAD + kg * 8) * 2;
            *(uint4*)(sm + SM_BH + so) = h;
            *(uint4*)(sm + SM_BL + so) = l;
        }
        __syncthreads();
#pragma unroll
        for (int k16 = 0; k16 < 8; k16++) {
            uint32_t kb2 = (uint32_t)(k16 * 16) * 2;
            uint32_t Ah[2][4], Bh[2][4], Bl[2][4];
#pragma unroll
            for (int mi = 0; mi < 2; mi++) {
                uint32_t ad = smb + a_base + (uint32_t)mi * (16 * APAD * 2) + kb2;
                LDSM4(Ah[mi], ad + SM_A);
            }
#pragma unroll
            for (int nj = 0; nj < 2; nj++) {
                uint32_t bd = smb + b_base + (uint32_t)nj * (16 * APAD * 2) + kb2;
                LDSM4(Bh[nj], bd + SM_BH);
                LDSM4(Bl[nj], bd + SM_BL);
            }
#pragma unroll
            for (int mi = 0; mi < 2; mi++)
#pragma unroll
                for (int nj = 0; nj < 2; nj++) {
                    MMA_F16(acc[mi][2 * nj + 0], Ah[mi], Bh[nj][0], Bh[nj][1]);
                    MMA_F16(acc[mi][2 * nj + 0], Ah[mi], Bl[nj][0], Bl[nj][1]);
                    MMA_F16(acc[mi][2 * nj + 1], Ah[mi], Bh[nj][2], Bh[nj][3]);
                    MMA_F16(acc[mi][2 * nj + 1], Ah[mi], Bl[nj][2], Bl[nj][3]);
                }
        }
    }

    // ---- fused epilogues ----
    __syncthreads();
    float* st = (float*)sm;
    int g = lane >> 2, t = lane & 3;

    if (mode == 2) {
#pragma unroll
        for (int mi = 0; mi < 2; mi++)
#pragma unroll
            for (int ni = 0; ni < 4; ni++) {
                int r = wm + mi * 16 + g;
                int c = wn + ni * 8 + t * 2;
                st[c * 132 + r]           = acc[mi][ni][0];
                st[(c + 1) * 132 + r]     = acc[mi][ni][1];
                st[c * 132 + r + 8]       = acc[mi][ni][2];
                st[(c + 1) * 132 + r + 8] = acc[mi][ni][3];
            }
        __syncthreads();
        int seq = m0 >> 7;
        int b = seq >> 7, y = seq & 127;
#pragma unroll
        for (int j = 0; j < 32; j++) {
            int idx = j * 256 + tid;
            int c = idx >> 7, xx = idx & 127;
            outp[(((size_t)b * 128 + n0 + c) * 128 + y) * 128 + xx] = st[c * 132 + xx];
        }
        return;
    }

    // mode 1: stage [l][e] (pad 72)
#pragma unroll
    for (int mi = 0; mi < 2; mi++)
#pragma unroll
        for (int ni = 0; ni < 4; ni++) {
            int r = wm + mi * 16 + g;
            int c = wn + ni * 8 + t * 2;
            *(float2*)&st[r * 72 + c] = make_float2(acc[mi][ni][0], acc[mi][ni][1]);
            *(float2*)&st[(r + 8) * 72 + c] = make_float2(acc[mi][ni][2], acc[mi][ni][3]);
        }
    __syncthreads();

    if (n0 < 256) {
        __half2* dst = (__half2*)g_z;
#pragma unroll
        for (int j = 0; j < 16; j++) {
            int idx = j * 256 + tid;
            int r = idx >> 5, cp = idx & 31;
            float2 v = *(float2*)&st[r * 72 + cp * 2];
            dst[(size_t)(m0 + r) * 128 + (n0 >> 1) + cp] = __floats2half2_rn(v.x, v.y);
        }
    } else if (n0 < 640) {
        int e2 = tid & 31;
        int ea = e2 * 2, eb = ea + 1;
        int eg = n0 - 256 + ea;
        float4 wA = *(const float4*)(cw + eg * 4);
        float4 wB = *(const float4*)(cw + eg * 4 + 4);
        float biaA = __ldg(cb + eg);
        float biaB = __ldg(cb + eg + 1);
        int lb = (tid >> 5) * 16;
        float a0 = (lb >= 3) ? st[(lb - 3) * 72 + ea] : 0.0f;
        float a1 = (lb >= 2) ? st[(lb - 2) * 72 + ea] : 0.0f;
        float a2 = (lb >= 1) ? st[(lb - 1) * 72 + ea] : 0.0f;
        float b0 = (lb >= 3) ? st[(lb - 3) * 72 + eb] : 0.0f;
        float b1 = (lb >= 2) ? st[(lb - 2) * 72 + eb] : 0.0f;
        float b2 = (lb >= 1) ? st[(lb - 1) * 72 + eb] : 0.0f;
        __half2* dst = (__half2*)g_xbcc;
        int colbase = ((n0 - 256) >> 1) + e2;
#pragma unroll 4
        for (int l = lb; l < lb + 16; l++) {
            float a3 = st[l * 72 + ea];
            float b3 = st[l * 72 + eb];
            float va = biaA + wA.x * a0 + wA.y * a1 + wA.z * a2 + wA.w * a3;
            float vb = biaB + wB.x * b0 + wB.y * b1 + wB.z * b2 + wB.w * b3;
            a0 = a1; a1 = a2; a2 = a3;
            b0 = b1; b1 = b2; b2 = b3;
            va = va / (1.0f + expf(-va));
            vb = vb / (1.0f + expf(-vb));
            dst[(size_t)(m0 + l) * 192 + colbase] = __floats2half2_rn(va, vb);
        }
    } else {
#pragma unroll
        for (int j = 0; j < 4; j++) {
            int idx = j * 256 + tid;
            int r = idx >> 3, hc = idx & 7;
            float v = st[r * 72 + hc] + __ldg(dtb + hc);
            g_dt[(size_t)(m0 + r) * 8 + hc] =
                fmaxf(v, 0.0f) + log1pf(expf(-fabsf(v)));
        }
    }
}

// ---------------------------------------------------------------------------
// K7: fused selective scan + gated RMSNorm, packed f32x2 inner loop (R13).
// ---------------------------------------------------------------------------
#define SCANORM_SMEM ((8192 + 8192 + 1024 + 1024 + 16) * 4)
__global__ __launch_bounds__(256) void k_scanorm(const float* __restrict__ A_log,
                                                 const float* __restrict__ Dskip,
                                                 const float* __restrict__ ng) {
    extern __shared__ float smf[];
    float* sB  = smf;
    float* sC  = sB + 8192;
    float* sdt = sC + 8192;
    float* sdA = sdt + 1024;
    float* pp  = sdA + 1024;
    int bs = blockIdx.x;
    int t = threadIdx.x;
    int hh = t >> 5;
    int lane = t & 31, wid = t >> 5;

    const __half* xb = g_xbcc + (size_t)bs * 128 * 384;
    const __half2* xb2 = (const __half2*)xb;
    for (int i = t; i < 4096; i += 256) {
        int l = i >> 5, s2 = i & 31;
        float2 fb = __half22float2(xb2[l * 192 + 128 + s2]);
        float2 fc = __half22float2(xb2[l * 192 + 160 + s2]);
        sB[l * 64 + 2 * s2]     = fb.x;
        sB[l * 64 + 2 * s2 + 1] = fb.y;
        sC[l * 64 + 2 * s2]     = fc.x;
        sC[l * 64 + 2 * s2 + 1] = fc.y;
    }
    for (int i = t; i < 1024; i += 256) {
        int l = i >> 3, h = i & 7;
        float v = g_dt[((size_t)bs * 128 + l) * 8 + h];
        sdt[i] = v;
        sdA[i] = expf(v * (-expf(__ldg(A_log + h))));
    }
    __syncthreads();

    float Dh = __ldg(Dskip + hh);
    float gn = __ldg(ng + t);
    unsigned long long h2[32];
#pragma unroll
    for (int s = 0; s < 32; s++) h2[s] = 0ULL;
    __half* yh = (__half*)g_y_h;

    for (int l = 0; l < 128; l++) {
        float xv  = __half2float(xb[l * 384 + t]);
        float z   = __half2float(g_z[((size_t)bs * 128 + l) * 256 + t]);
        float dtv = sdt[l * 8 + hh];
        float dA  = sdA[l * 8 + hh];
        float cf  = dtv * xv;
        unsigned long long dA2 = pk2(dA, dA);
        unsigned long long cf2 = pk2(cf, cf);
        const unsigned long long* B2 = (const unsigned long long*)(sB + l * 64);
        const unsigned long long* C2 = (const unsigned long long*)(sC + l * 64);
        unsigned long long y2 = 0ULL;
#pragma unroll
        for (int s = 0; s < 32; s++) {
            unsigned long long bb = B2[s], cc = C2[s], u;
            MUL2(u, cf2, bb);
            FMA2(h2[s], h2[s], dA2, u);
            FMA2(y2, h2[s], cc, y2);
        }
        float y0, y1;
        upk2(y2, y0, y1);
        float y = (y0 + y1) + Dh * xv;
        float gv = y * (z / (1.0f + expf(-z)));
        float g2 = gv * gv;
#pragma unroll
        for (int o = 16; o > 0; o >>= 1) g2 += __shfl_xor_sync(0xffffffffu, g2, o);
        float* ppb = pp + (l & 1) * 8;
        if (lane == 0) ppb[wid] = g2;
        __syncthreads();
        float sum = ppb[0] + ppb[1] + ppb[2] + ppb[3] +
                    ppb[4] + ppb[5] + ppb[6] + ppb[7];
        float sc = rsqrtf(sum * (1.0f / 256.0f) + 1e-5f);
        yh[((size_t)bs * 128 + l) * 256 + t] = __float2half(gv * sc * gn);
    }
}

// ---------------------------------------------------------------------------
extern "C" void kernel_launch(void* const* d_in, const int* in_sizes, int n_in,
                              void* d_out, int out_size) {
    const float* x        = (const float*)d_in[0];
    const float* dw_w     = (const float*)d_in[1];
    const float* gn_g     = (const float*)d_in[2];
    const float* gn_b     = (const float*)d_in[3];
    const float* pw_w     = (const float*)d_in[4];
    const float* pw_b     = (const float*)d_in[5];
    const float* in_projw = (const float*)d_in[6];
    const float* conv_w   = (const float*)d_in[7];
    const float* conv_b   = (const float*)d_in[8];
    const float* dt_bias  = (const float*)d_in[9];
    const float* A_log    = (const float*)d_in[10];
    const float* D_skip   = (const float*)d_in[11];
    const float* norm_g   = (const float*)d_in[12];
    const float* out_w    = (const float*)d_in[13];
    float* out = (float*)d_out;

    float* p_off;
    uint4 *p_sh, *p_yh, *p_iph, *p_ipl, *p_owh, *p_owl;
    cudaGetSymbolAddress((void**)&p_off, g_off);
    cudaGetSymbolAddress((void**)&p_sh, g_seq_h);
    cudaGetSymbolAddress((void**)&p_yh, g_y_h);
    cudaGetSymbolAddress((void**)&p_iph, g_ipw_hi);
    cudaGetSymbolAddress((void**)&p_ipl, g_ipw_lo);
    cudaGetSymbolAddress((void**)&p_owh, g_ow_hi);
    cudaGetSymbolAddress((void**)&p_owl, g_ow_lo);

    cudaFuncSetAttribute(k_gemm, cudaFuncAttributeMaxDynamicSharedMemorySize, SMEM_GEMM);
    cudaFuncSetAttribute(k_scanorm, cudaFuncAttributeMaxDynamicSharedMemorySize, SCANORM_SMEM);

    k_dwconv<<<OUT2D_ELEMS / 4 / 256, 256>>>(x, dw_w);
    k_gnstats1<<<dim3(64, 8), 256>>>();
    k_offset<<<OFF_ELEMS / 1024, 256>>>(gn_g, gn_b, pw_w, pw_b);
    k_sample<<<dim3(BS, 2), 256>>>(x);
    k_wsplit<<<(IPW_ELEMS + 255) / 256, 256>>>(in_projw, p_iph, p_ipl, IPW_ELEMS);

    // in_proj: (M=131072, N=648, K=128) + fused conv1d/silu/dt epilogue
    k_gemm<<<dim3((D_INPROJ + 63) / 64, MM / 128), 256, SMEM_GEMM>>>(
        p_sh, p_iph, p_ipl, nullptr, conv_w, conv_b, dt_bias,
        D_INPROJ, 128, 1);

    k_wsplit<<<(OW_ELEMS + 255) / 256, 256>>>(out_w, p_owh, p_owl, OW_ELEMS);

    // fused scan + gated RMSNorm (packed f32x2)
    k_scanorm<<<BS, 256, SCANORM_SMEM>>>(A_log, D_skip, norm_g);

    // out proj: (M=131072, N=128, K=256) + fused NCHW epilogue
    k_gemm<<<dim3(2, MM / 128), 256, SMEM_GEMM>>>(
        p_yh, p_owh, p_owl, out, nullptr, nullptr, nullptr,
        128, 256, 2);

    if (out_size >= OUT2D_ELEMS + OFF_ELEMS)
        cudaMemcpyAsync(out + OUT2D_ELEMS, p_off, OFF_ELEMS * sizeof(float),
                        cudaMemcpyDeviceToDevice);
}

// round 17
// speedup vs baseline: 1.4229x; 1.0440x over previous
#include <cuda_runtime.h>
#include <cuda_bf16.h>
#include <cuda_fp16.h>
#include <math.h>
#include <stdint.h>

// ---------------------------------------------------------------------------
// SnakeScanBranch R16: R13 baseline + scanorm load pipelining (exact) +
// single-product weights in the out GEMM (y is already fp16-rounded).
// ---------------------------------------------------------------------------

#define Bb 8
#define Cc 128
#define Hh 128
#define Ww 128
#define HW 16384
#define D_INNER 256
#define D_STATE 64
#define NHEADS 8
#define D_XBC 384
#define D_INPROJ 648
#define BS 1024
#define LL 128
#define MM 131072
#define OUT2D_ELEMS 16777216
#define OFF_ELEMS 131072
#define IPW_ELEMS (D_INPROJ * 128)
#define OW_ELEMS  (128 * D_INNER)

// ---- scratch ---------------------------------------------------------------
__device__ float g_buf1[OUT2D_ELEMS];            // dwconv output (fp32)
__device__ __half g_z[(size_t)MM * 256];         // z (fp16)
__device__ __half g_xbcc[(size_t)MM * D_XBC];    // conv1d+silu output (fp16)
__device__ float g_dt[MM * NHEADS];
__device__ float g_off[OFF_ELEMS];
__device__ float g_part[64 * 8 * 2];
__device__ uint4 g_seq_h[(size_t)MM * 128 / 8];  // fp16 seq
__device__ uint4 g_y_h[(size_t)MM * 256 / 8];    // fp16 normalized y
__device__ uint4 g_ipw_hi[IPW_ELEMS / 8];
__device__ uint4 g_ipw_lo[IPW_ELEMS / 8];
__device__ uint4 g_ow_hi[OW_ELEMS / 8];
__device__ uint4 g_ow_lo[OW_ELEMS / 8];

// ---------------------------------------------------------------------------
__device__ __forceinline__ uint32_t smem_u32(const void* p) {
    uint32_t a;
    asm("{ .reg .u64 t; cvta.to.shared.u64 t, %1; cvt.u32.u64 %0, t; }"
        : "=r"(a) : "l"(p));
    return a;
}

#define LDSM4(r, addr)                                                        \
    asm volatile("ldmatrix.sync.aligned.m8n8.x4.shared.b16 {%0,%1,%2,%3}, [%4];" \
                 : "=r"((r)[0]), "=r"((r)[1]), "=r"((r)[2]), "=r"((r)[3])     \
                 : "r"(addr))

#define MMA_F16(d, a, b0, b1)                                                 \
    asm volatile(                                                             \
        "mma.sync.aligned.m16n8k16.row.col.f32.f16.f16.f32 "                  \
        "{%0,%1,%2,%3}, {%4,%5,%6,%7}, {%8,%9}, {%0,%1,%2,%3};"               \
        : "+f"((d)[0]), "+f"((d)[1]), "+f"((d)[2]), "+f"((d)[3])              \
        : "r"((a)[0]), "r"((a)[1]), "r"((a)[2]), "r"((a)[3]), "r"(b0), "r"(b1))

// packed f32x2 helpers
__device__ __forceinline__ unsigned long long pk2(float lo, float hi) {
    unsigned long long r;
    asm("mov.b64 %0, {%1, %2};" : "=l"(r) : "f"(lo), "f"(hi));
    return r;
}
__device__ __forceinline__ void upk2(unsigned long long v, float& lo, float& hi) {
    asm("mov.b64 {%0, %1}, %2;" : "=f"(lo), "=f"(hi) : "l"(v));
}
#define FMA2(d, a, b, c) \
    asm("fma.rn.f32x2 %0, %1, %2, %3;" : "=l"(d) : "l"(a), "l"(b), "l"(c))
#define MUL2(d, a, b) \
    asm("mul.rn.f32x2 %0, %1, %2;" : "=l"(d) : "l"(a), "l"(b))

// ---------------------------------------------------------------------------
// K1: depthwise 5x5 conv — 4 outputs/thread along y (row-tap reuse)
// ---------------------------------------------------------------------------
__global__ __launch_bounds__(256) void k_dwconv(const float* __restrict__ x,
                                                const float* __restrict__ w) {
    int idx = blockIdx.x * 256 + threadIdx.x;
    int xx = idx & 127;
    int yg = (idx >> 7) & 31;
    int c  = (idx >> 12) & 127;
    int b  = idx >> 19;
    int y0 = yg * 4;
    float wr[25];
#pragma unroll
    for (int i = 0; i < 25; i++) wr[i] = __ldg(w + c * 25 + i);
    const float* plane = x + ((size_t)b * Cc + c) * HW;
    float o0 = 0.f, o1 = 0.f, o2 = 0.f, o3 = 0.f;
#pragma unroll
    for (int r = 0; r < 8; r++) {
        int sy = y0 + r - 2;
        if (sy < 0 || sy > 127) continue;
        const float* row = plane + sy * Ww;
        float v0 = (xx >= 2)   ? __ldg(row + xx - 2) : 0.f;
        float v1 = (xx >= 1)   ? __ldg(row + xx - 1) : 0.f;
        float v2 = __ldg(row + xx);
        float v3 = (xx <= 126) ? __ldg(row + xx + 1) : 0.f;
        float v4 = (xx <= 125) ? __ldg(row + xx + 2) : 0.f;
#define RS(ky) (v0 * wr[(ky) * 5 + 0] + v1 * wr[(ky) * 5 + 1] +               \
                v2 * wr[(ky) * 5 + 2] + v3 * wr[(ky) * 5 + 3] +               \
                v4 * wr[(ky) * 5 + 4])
        if (r <= 4)           o0 += RS(r);
        if (r >= 1 && r <= 5) o1 += RS(r - 1);
        if (r >= 2 && r <= 6) o2 += RS(r - 2);
        if (r >= 3)           o3 += RS(r - 3);
#undef RS
    }
    float* dst = g_buf1 + ((size_t)b * Cc + c) * HW + y0 * Ww + xx;
    dst[0]       = o0;
    dst[Ww]      = o1;
    dst[2 * Ww]  = o2;
    dst[3 * Ww]  = o3;
}

// ---------------------------------------------------------------------------
// K2: groupnorm partial sums (float4 streaming)
// ---------------------------------------------------------------------------
__global__ __launch_bounds__(256) void k_gnstats1() {
    int bg = blockIdx.x;
    int part = blockIdx.y;
    const float4* p = (const float4*)(g_buf1 + (size_t)bg * 16 * HW + part * 32768);
    float s = 0.0f, ss = 0.0f;
    for (int i = threadIdx.x; i < 8192; i += 256) {
        float4 v = p[i];
        s  += (v.x + v.y) + (v.z + v.w);
        ss += (v.x * v.x + v.y * v.y) + (v.z * v.z + v.w * v.w);
    }
    __shared__ float rs[256], rss[256];
    rs[threadIdx.x] = s; rss[threadIdx.x] = ss;
    __syncthreads();
    for (int o = 128; o > 0; o >>= 1) {
        if (threadIdx.x < o) { rs[threadIdx.x] += rs[threadIdx.x + o]; rss[threadIdx.x] += rss[threadIdx.x + o]; }
        __syncthreads();
    }
    if (threadIdx.x == 0) {
        g_part[(bg * 8 + part) * 2]     = rs[0];
        g_part[(bg * 8 + part) * 2 + 1] = rss[0];
    }
}

// ---------------------------------------------------------------------------
// K3: finalize stats + gelu(gn) -> pointwise -> tanh*8  (2 px/thread, float2)
// ---------------------------------------------------------------------------
__global__ __launch_bounds__(256) void k_offset(const float* __restrict__ gn_g,
                                                const float* __restrict__ gn_b,
                                                const float* __restrict__ pw_w,
                                                const float* __restrict__ pw_b) {
    __shared__ float s_mean[8], s_rstd[8];
    int base = blockIdx.x * 512;
    int b = base >> 14;
    if (threadIdx.x < 8) {
        int gg = threadIdx.x;
        float s = 0.0f, ss = 0.0f;
        for (int p = 0; p < 8; p++) {
            s  += g_part[((b * 8 + gg) * 8 + p) * 2];
            ss += g_part[((b * 8 + gg) * 8 + p) * 2 + 1];
        }
        const float inv = 1.0f / (16.0f * HW);
        float mean = s * inv;
        float var  = ss * inv - mean * mean;
        s_mean[gg] = mean;
        s_rstd[gg] = rsqrtf(var + 1e-5f);
    }
    __syncthreads();
    int pixl = (base & 16383) + threadIdx.x * 2;
    const float* pb = g_buf1 + (size_t)b * Cc * HW + pixl;
    float a0 = 0.0f, a1 = 0.0f;
    for (int c = 0; c < Cc; c++) {
        float2 v = *(const float2*)(pb + (size_t)c * HW);
        int grp = c >> 4;
        float mean = s_mean[grp], rstd = s_rstd[grp];
        float gw = __ldg(gn_g + c), gb = __ldg(gn_b + c);
        float pw = __ldg(pw_w + c);
        float u0 = (v.x - mean) * rstd * gw + gb;
        float u1 = (v.y - mean) * rstd * gw + gb;
        a0 += pw * (0.5f * u0 * (1.0f + erff(u0 * 0.70710678118654752440f)));
        a1 += pw * (0.5f * u1 * (1.0f + erff(u1 * 0.70710678118654752440f)));
    }
    float pb0 = __ldg(pw_b);
    int po = base + threadIdx.x * 2;
    g_off[po]     = tanhf(a0 + pb0) * 8.0f;
    g_off[po + 1] = tanhf(a1 + pb0) * 8.0f;
}

// ---------------------------------------------------------------------------
// K4: grid sample (bilinear, border) -> seq fp16 (half2 stores)
// ---------------------------------------------------------------------------
__global__ __launch_bounds__(256) void k_sample(const float* __restrict__ x) {
    int by = blockIdx.x;
    int b = by >> 7, y = by & 127;
    int x0g = blockIdx.y * 64;
    __shared__ float tile[64][129];
    __shared__ int s_y0[64], s_y1[64], s_x0[64], s_x1[64];
    __shared__ float s_wx[64], s_wy[64];
    int tid = threadIdx.x;
    if (tid < 64) {
        int xg = x0g + tid;
        float off_n = g_off[by * Ww + xg] * (2.0f / 127.0f);
        float byv = -1.0f + y  * (2.0f / 127.0f);
        float bxv = -1.0f + xg * (2.0f / 127.0f);
        float gyv = fminf(fmaxf(byv + off_n, -1.0f), 1.0f);
        float gx = fminf(fmaxf((bxv + 1.0f) * 0.5f * 127.0f, 0.0f), 127.0f);
        float gy = fminf(fmaxf((gyv + 1.0f) * 0.5f * 127.0f, 0.0f), 127.0f);
        float fx0 = floorf(gx), fy0 = floorf(gy);
        s_wx[tid] = gx - fx0;
        s_wy[tid] = gy - fy0;
        int x0i = (int)fx0, y0i = (int)fy0;
        s_x0[tid] = x0i; s_y0[tid] = y0i;
        s_x1[tid] = min(x0i + 1, 127);
        s_y1[tid] = min(y0i + 1, 127);
    }
    __syncthreads();
    for (int i = tid; i < 64 * Cc; i += 256) {
        int xl = i & 63;
        int c = i >> 6;
        const float* pl = x + ((size_t)b * Cc + c) * HW;
        float wx = s_wx[xl], wy = s_wy[xl];
        int r0 = s_y0[xl] * Ww, r1 = s_y1[xl] * Ww;
        float v00 = __ldg(pl + r0 + s_x0[xl]);
        float v01 = __ldg(pl + r0 + s_x1[xl]);
        float v10 = __ldg(pl + r1 + s_x0[xl]);
        float v11 = __ldg(pl + r1 + s_x1[xl]);
        float top = v00 * (1.0f - wx) + v01 * wx;
        float bot = v10 * (1.0f - wx) + v11 * wx;
        tile[xl][c] = top * (1.0f - wy) + bot * wy;
    }
    __syncthreads();
    __half2* sh2 = (__half2*)g_seq_h;
    for (int i = tid; i < 64 * 64; i += 256) {
        int xl = i >> 6;
        int c2 = i & 63;
        __half2 hv = __floats2half2_rn(tile[xl][c2 * 2], tile[xl][c2 * 2 + 1]);
        sh2[((size_t)by * Ww + x0g + xl) * 64 + c2] = hv;
    }
}

// ---------------------------------------------------------------------------
// Weight split fp32 -> fp16 hi + fp16 lo
// ---------------------------------------------------------------------------
__global__ __launch_bounds__(256) void k_wsplit(const float* __restrict__ w,
                                                uint4* __restrict__ hi4,
                                                uint4* __restrict__ lo4, int n) {
    int i = blockIdx.x * 256 + threadIdx.x;
    if (i >= n) return;
    float v = w[i];
    __half h = __float2half(v);
    __half l = __float2half(v - __half2float(h));
    ((__half*)hi4)[i] = h;
    ((__half*)lo4)[i] = l;
}

// ---------------------------------------------------------------------------
// fp16 GEMM: mode 1 (in_proj) = 2-product weights + fused conv1d/silu/dt.
// mode 2 (out proj) = single-product weights + direct NCHW epilogue.
// ---------------------------------------------------------------------------
#define APAD 136
#define SM_A  0
#define SM_BH 34816
#define SM_BL 52224
#define SMEM_GEMM 69632

__global__ __launch_bounds__(256) void k_gemm(const uint4* __restrict__ A,
                                              const uint4* __restrict__ Bhi,
                                              const uint4* __restrict__ Blo,
                                              float* __restrict__ outp,
                                              const float* __restrict__ cw,
                                              const float* __restrict__ cb,
                                              const float* __restrict__ dtb,
                                              int N, int K, int mode) {
    extern __shared__ char sm[];
    uint32_t smb = smem_u32(sm);
    int tid = threadIdx.x;
    int lane = tid & 31;
    int wid = tid >> 5;
    int wm = (wid >> 1) * 32;
    int wn = (wid & 1) * 32;
    int m0 = blockIdx.y * 128;
    int n0 = blockIdx.x * 64;
    int K8 = K >> 3;
    bool twoprod = (mode == 1);

    float acc[2][4][4];
#pragma unroll
    for (int mi = 0; mi < 2; mi++)
#pragma unroll
        for (int ni = 0; ni < 4; ni++)
#pragma unroll
            for (int j = 0; j < 4; j++) acc[mi][ni][j] = 0.0f;

    int a_r  = lane & 15;
    int a_c8 = (lane >> 4) << 3;
    uint32_t a_base = ((uint32_t)(wm + a_r) * APAD + a_c8) * 2;
    int b_r  = (lane & 7) + ((lane >> 4) << 3);
    int b_c8 = ((lane >> 3) & 1) << 3;
    uint32_t b_base = ((uint32_t)(wn + b_r) * APAD + b_c8) * 2;

    int nchunks = K >> 7;
    for (int ch = 0; ch < nchunks; ch++) {
        if (ch) __syncthreads();
        int kc8 = ch << 4;
#pragma unroll
        for (int it = 0; it < 8; it++) {
            int g = it * 256 + tid;
            int row = g >> 4, kg = g & 15;
            size_t go = (size_t)(m0 + row) * K8 + kc8 + kg;
            uint32_t so = ((uint32_t)row * APAD + kg * 8) * 2;
            *(uint4*)(sm + SM_A + so) = A[go];
        }
#pragma unroll
        for (int it = 0; it < 4; it++) {
            int g = it * 256 + tid;
            int row = g >> 4, kg = g & 15;
            uint4 h = make_uint4(0, 0, 0, 0), l = make_uint4(0, 0, 0, 0);
            if (n0 + row < N) {
                size_t go = (size_t)(n0 + row) * K8 + kc8 + kg;
                h = Bhi[go];
                if (twoprod) l = Blo[go];
            }
            uint32_t so = ((uint32_t)row * APAD + kg * 8) * 2;
            *(uint4*)(sm + SM_BH + so) = h;
            if (twoprod) *(uint4*)(sm + SM_BL + so) = l;
        }
        __syncthreads();
#pragma unroll
        for (int k16 = 0; k16 < 8; k16++) {
            uint32_t kb2 = (uint32_t)(k16 * 16) * 2;
            uint32_t Ah[2][4], Bh[2][4], Bl[2][4];
#pragma unroll
            for (int mi = 0; mi < 2; mi++) {
                uint32_t ad = smb + a_base + (uint32_t)mi * (16 * APAD * 2) + kb2;
                LDSM4(Ah[mi], ad + SM_A);
            }
#pragma unroll
            for (int nj = 0; nj < 2; nj++) {
                uint32_t bd = smb + b_base + (uint32_t)nj * (16 * APAD * 2) + kb2;
                LDSM4(Bh[nj], bd + SM_BH);
                if (twoprod) LDSM4(Bl[nj], bd + SM_BL);
            }
#pragma unroll
            for (int mi = 0; mi < 2; mi++)
#pragma unroll
                for (int nj = 0; nj < 2; nj++) {
                    MMA_F16(acc[mi][2 * nj + 0], Ah[mi], Bh[nj][0], Bh[nj][1]);
                    MMA_F16(acc[mi][2 * nj + 1], Ah[mi], Bh[nj][2], Bh[nj][3]);
                    if (twoprod) {
                        MMA_F16(acc[mi][2 * nj + 0], Ah[mi], Bl[nj][0], Bl[nj][1]);
                        MMA_F16(acc[mi][2 * nj + 1], Ah[mi], Bl[nj][2], Bl[nj][3]);
                    }
                }
        }
    }

    // ---- fused epilogues ----
    __syncthreads();
    float* st = (float*)sm;
    int g = lane >> 2, t = lane & 3;

    if (mode == 2) {
#pragma unroll
        for (int mi = 0; mi < 2; mi++)
#pragma unroll
            for (int ni = 0; ni < 4; ni++) {
                int r = wm + mi * 16 + g;
                int c = wn + ni * 8 + t * 2;
                st[c * 132 + r]           = acc[mi][ni][0];
                st[(c + 1) * 132 + r]     = acc[mi][ni][1];
                st[c * 132 + r + 8]       = acc[mi][ni][2];
                st[(c + 1) * 132 + r + 8] = acc[mi][ni][3];
            }
        __syncthreads();
        int seq = m0 >> 7;
        int b = seq >> 7, y = seq & 127;
#pragma unroll
        for (int j = 0; j < 32; j++) {
            int idx = j * 256 + tid;
            int c = idx >> 7, xx = idx & 127;
            outp[(((size_t)b * 128 + n0 + c) * 128 + y) * 128 + xx] = st[c * 132 + xx];
        }
        return;
    }

    // mode 1: stage [l][e] (pad 72)
#pragma unroll
    for (int mi = 0; mi < 2; mi++)
#pragma unroll
        for (int ni = 0; ni < 4; ni++) {
            int r = wm + mi * 16 + g;
            int c = wn + ni * 8 + t * 2;
            *(float2*)&st[r * 72 + c] = make_float2(acc[mi][ni][0], acc[mi][ni][1]);
            *(float2*)&st[(r + 8) * 72 + c] = make_float2(acc[mi][ni][2], acc[mi][ni][3]);
        }
    __syncthreads();

    if (n0 < 256) {
        __half2* dst = (__half2*)g_z;
#pragma unroll
        for (int j = 0; j < 16; j++) {
            int idx = j * 256 + tid;
            int r = idx >> 5, cp = idx & 31;
            float2 v = *(float2*)&st[r * 72 + cp * 2];
            dst[(size_t)(m0 + r) * 128 + (n0 >> 1) + cp] = __floats2half2_rn(v.x, v.y);
        }
    } else if (n0 < 640) {
        int e2 = tid & 31;
        int ea = e2 * 2, eb = ea + 1;
        int eg = n0 - 256 + ea;
        float4 wA = *(const float4*)(cw + eg * 4);
        float4 wB = *(const float4*)(cw + eg * 4 + 4);
        float biaA = __ldg(cb + eg);
        float biaB = __ldg(cb + eg + 1);
        int lb = (tid >> 5) * 16;
        float a0 = (lb >= 3) ? st[(lb - 3) * 72 + ea] : 0.0f;
        float a1 = (lb >= 2) ? st[(lb - 2) * 72 + ea] : 0.0f;
        float a2 = (lb >= 1) ? st[(lb - 1) * 72 + ea] : 0.0f;
        float b0 = (lb >= 3) ? st[(lb - 3) * 72 + eb] : 0.0f;
        float b1 = (lb >= 2) ? st[(lb - 2) * 72 + eb] : 0.0f;
        float b2 = (lb >= 1) ? st[(lb - 1) * 72 + eb] : 0.0f;
        __half2* dst = (__half2*)g_xbcc;
        int colbase = ((n0 - 256) >> 1) + e2;
#pragma unroll 4
        for (int l = lb; l < lb + 16; l++) {
            float a3 = st[l * 72 + ea];
            float b3 = st[l * 72 + eb];
            float va = biaA + wA.x * a0 + wA.y * a1 + wA.z * a2 + wA.w * a3;
            float vb = biaB + wB.x * b0 + wB.y * b1 + wB.z * b2 + wB.w * b3;
            a0 = a1; a1 = a2; a2 = a3;
            b0 = b1; b1 = b2; b2 = b3;
            va = va / (1.0f + expf(-va));
            vb = vb / (1.0f + expf(-vb));
            dst[(size_t)(m0 + l) * 192 + colbase] = __floats2half2_rn(va, vb);
        }
    } else {
#pragma unroll
        for (int j = 0; j < 4; j++) {
            int idx = j * 256 + tid;
            int r = idx >> 3, hc = idx & 7;
            float v = st[r * 72 + hc] + __ldg(dtb + hc);
            g_dt[(size_t)(m0 + r) * 8 + hc] =
                fmaxf(v, 0.0f) + log1pf(expf(-fabsf(v)));
        }
    }
}

// ---------------------------------------------------------------------------
// K7: fused selective scan + gated RMSNorm, packed f32x2 inner loop,
// xv/z loads software-pipelined one timestep ahead (exact).
// ---------------------------------------------------------------------------
#define SCANORM_SMEM ((8192 + 8192 + 1024 + 1024 + 16) * 4)
__global__ __launch_bounds__(256) void k_scanorm(const float* __restrict__ A_log,
                                                 const float* __restrict__ Dskip,
                                                 const float* __restrict__ ng) {
    extern __shared__ float smf[];
    float* sB  = smf;
    float* sC  = sB + 8192;
    float* sdt = sC + 8192;
    float* sdA = sdt + 1024;
    float* pp  = sdA + 1024;
    int bs = blockIdx.x;
    int t = threadIdx.x;
    int hh = t >> 5;
    int lane = t & 31, wid = t >> 5;

    const __half* xb = g_xbcc + (size_t)bs * 128 * 384;
    const __half2* xb2 = (const __half2*)xb;
    for (int i = t; i < 4096; i += 256) {
        int l = i >> 5, s2 = i & 31;
        float2 fb = __half22float2(xb2[l * 192 + 128 + s2]);
        float2 fc = __half22float2(xb2[l * 192 + 160 + s2]);
        sB[l * 64 + 2 * s2]     = fb.x;
        sB[l * 64 + 2 * s2 + 1] = fb.y;
        sC[l * 64 + 2 * s2]     = fc.x;
        sC[l * 64 + 2 * s2 + 1] = fc.y;
    }
    for (int i = t; i < 1024; i += 256) {
        int l = i >> 3, h = i & 7;
        float v = g_dt[((size_t)bs * 128 + l) * 8 + h];
        sdt[i] = v;
        sdA[i] = expf(v * (-expf(__ldg(A_log + h))));
    }
    __syncthreads();

    float Dh = __ldg(Dskip + hh);
    float gn = __ldg(ng + t);
    unsigned long long h2[32];
#pragma unroll
    for (int s = 0; s < 32; s++) h2[s] = 0ULL;
    __half* yh = (__half*)g_y_h;
    const __half* zp = g_z + (size_t)bs * 128 * 256 + t;

    // prologue loads for l = 0
    __half xv_h = xb[t];
    __half z_h  = zp[0];

    for (int l = 0; l < 128; l++) {
        float xv = __half2float(xv_h);
        float z  = __half2float(z_h);
        // prefetch next timestep's loads; they complete under the FMA chain
        if (l < 127) {
            xv_h = xb[(l + 1) * 384 + t];
            z_h  = zp[(size_t)(l + 1) * 256];
        }
        float dtv = sdt[l * 8 + hh];
        float dA  = sdA[l * 8 + hh];
        float cf  = dtv * xv;
        unsigned long long dA2 = pk2(dA, dA);
        unsigned long long cf2 = pk2(cf, cf);
        const unsigned long long* B2 = (const unsigned long long*)(sB + l * 64);
        const unsigned long long* C2 = (const unsigned long long*)(sC + l * 64);
        unsigned long long y2 = 0ULL;
#pragma unroll
        for (int s = 0; s < 32; s++) {
            unsigned long long bb = B2[s], cc = C2[s], u;
            MUL2(u, cf2, bb);
            FMA2(h2[s], h2[s], dA2, u);
            FMA2(y2, h2[s], cc, y2);
        }
        float y0, y1;
        upk2(y2, y0, y1);
        float y = (y0 + y1) + Dh * xv;
        float gv = y * (z / (1.0f + expf(-z)));
        float g2 = gv * gv;
#pragma unroll
        for (int o = 16; o > 0; o >>= 1) g2 += __shfl_xor_sync(0xffffffffu, g2, o);
        float* ppb = pp + (l & 1) * 8;
        if (lane == 0) ppb[wid] = g2;
        __syncthreads();
        float sum = ppb[0] + ppb[1] + ppb[2] + ppb[3] +
                    ppb[4] + ppb[5] + ppb[6] + ppb[7];
        float sc = rsqrtf(sum * (1.0f / 256.0f) + 1e-5f);
        yh[((size_t)bs * 128 + l) * 256 + t] = __float2half(gv * sc * gn);
    }
}

// ---------------------------------------------------------------------------
extern "C" void kernel_launch(void* const* d_in, const int* in_sizes, int n_in,
                              void* d_out, int out_size) {
    const float* x        = (const float*)d_in[0];
    const float* dw_w     = (const float*)d_in[1];
    const float* gn_g     = (const float*)d_in[2];
    const float* gn_b     = (const float*)d_in[3];
    const float* pw_w     = (const float*)d_in[4];
    const float* pw_b     = (const float*)d_in[5];
    const float* in_projw = (const float*)d_in[6];
    const float* conv_w   = (const float*)d_in[7];
    const float* conv_b   = (const float*)d_in[8];
    const float* dt_bias  = (const float*)d_in[9];
    const float* A_log    = (const float*)d_in[10];
    const float* D_skip   = (const float*)d_in[11];
    const float* norm_g   = (const float*)d_in[12];
    const float* out_w    = (const float*)d_in[13];
    float* out = (float*)d_out;

    float* p_off;
    uint4 *p_sh, *p_yh, *p_iph, *p_ipl, *p_owh, *p_owl;
    cudaGetSymbolAddress((void**)&p_off, g_off);
    cudaGetSymbolAddress((void**)&p_sh, g_seq_h);
    cudaGetSymbolAddress((void**)&p_yh, g_y_h);
    cudaGetSymbolAddress((void**)&p_iph, g_ipw_hi);
    cudaGetSymbolAddress((void**)&p_ipl, g_ipw_lo);
    cudaGetSymbolAddress((void**)&p_owh, g_ow_hi);
    cudaGetSymbolAddress((void**)&p_owl, g_ow_lo);

    cudaFuncSetAttribute(k_gemm, cudaFuncAttributeMaxDynamicSharedMemorySize, SMEM_GEMM);
    cudaFuncSetAttribute(k_scanorm, cudaFuncAttributeMaxDynamicSharedMemorySize, SCANORM_SMEM);

    k_dwconv<<<OUT2D_ELEMS / 4 / 256, 256>>>(x, dw_w);
    k_gnstats1<<<dim3(64, 8), 256>>>();
    k_offset<<<OFF_ELEMS / 512, 256>>>(gn_g, gn_b, pw_w, pw_b);
    k_sample<<<dim3(BS, 2), 256>>>(x);
    k_wsplit<<<(IPW_ELEMS + 255) / 256, 256>>>(in_projw, p_iph, p_ipl, IPW_ELEMS);

    // in_proj: (M=131072, N=648, K=128) + fused conv1d/silu/dt epilogue
    k_gemm<<<dim3((D_INPROJ + 63) / 64, MM / 128), 256, SMEM_GEMM>>>(
        p_sh, p_iph, p_ipl, nullptr, conv_w, conv_b, dt_bias,
        D_INPROJ, 128, 1);

    k_wsplit<<<(OW_ELEMS + 255) / 256, 256>>>(out_w, p_owh, p_owl, OW_ELEMS);

    // fused scan + gated RMSNorm (packed f32x2, pipelined loads)
    k_scanorm<<<BS, 256, SCANORM_SMEM>>>(A_log, D_skip, norm_g);

    // out proj: (M=131072, N=128, K=256), single-product, NCHW epilogue
    k_gemm<<<dim3(2, MM / 128), 256, SMEM_GEMM>>>(
        p_yh, p_owh, p_owl, out, nullptr, nullptr, nullptr,
        128, 256, 2);

    if (out_size >= OUT2D_ELEMS + OFF_ELEMS)
        cudaMemcpyAsync(out + OUT2D_ELEMS, p_off, OFF_ELEMS * sizeof(float),
                        cudaMemcpyDeviceToDevice);
}